// round 1
// baseline (speedup 1.0000x reference)
#include <cuda_runtime.h>
#include <math.h>

#define B_    16
#define D_    100000
#define M_    128
#define NBIN_ 25

// scratch (allocation-free rule: __device__ globals)
__device__ float g_hlab[B_ * NBIN_];
__device__ float g_hall[B_ * NBIN_];
__device__ float g_labsum[B_];
__device__ float g_qn[B_];

// ---------------- kernel 1: zero accumulators + query norms ----------------
__global__ void qap_init(const float* __restrict__ qX) {
    int t = threadIdx.x;
    if (t < B_ * NBIN_) { g_hlab[t] = 0.0f; g_hall[t] = 0.0f; }
    if (t < B_) g_labsum[t] = 0.0f;
    int w = t >> 5, lane = t & 31;
    if (w < B_) {
        float4 v = reinterpret_cast<const float4*>(qX + w * M_)[lane];
        float s = v.x * v.x + v.y * v.y + v.z * v.z + v.w * v.w;
        #pragma unroll
        for (int o = 16; o; o >>= 1) s += __shfl_xor_sync(0xFFFFFFFFu, s, o);
        if (lane == 0) g_qn[w] = sqrtf(s);
    }
}

// ---------------- kernel 2: main accumulation (HBM-bound) ----------------
__global__ void __launch_bounds__(256) qap_accum(const float* __restrict__ qX,
                                                 const float* __restrict__ dXs,
                                                 const int*   __restrict__ labels) {
    const int b    = blockIdx.y;
    const int tid  = threadIdx.x;
    const int lane = tid & 31;
    const int warp = tid >> 5;

    __shared__ float s_hlab[NBIN_];
    __shared__ float s_hall[NBIN_];
    __shared__ float s_wlab[8];

    if (tid < NBIN_) { s_hlab[tid] = 0.0f; s_hall[tid] = 0.0f; }
    __syncthreads();

    const float4 qv = __ldg(&reinterpret_cast<const float4*>(qX + b * M_)[lane]);
    const float  qn = g_qn[b];
    const float4* __restrict__ dv = reinterpret_cast<const float4*>(dXs + (size_t)b * D_ * M_);
    const int*    __restrict__ lb = labels + b * D_;

    const int wid    = blockIdx.x * 8 + warp;   // warp id within batch
    const int stride = gridDim.x * 8;
    const float invDelta = (NBIN_ - 1) * 0.5f;  // 12
    float labcnt = 0.0f;

    for (int d0 = wid * 4; d0 < D_; d0 += stride * 4) {
        float dot0 = 0.f, dot1 = 0.f, dot2 = 0.f, dot3 = 0.f;
        float nr0  = 0.f, nr1  = 0.f, nr2  = 0.f, nr3  = 0.f;

        // front-batched coalesced loads: 4 docs x 16B/lane
        if (d0 + 0 < D_) { float4 v = dv[(size_t)(d0 + 0) * 32 + lane];
            dot0 = qv.x*v.x + qv.y*v.y + qv.z*v.z + qv.w*v.w;
            nr0  = v.x*v.x + v.y*v.y + v.z*v.z + v.w*v.w; }
        if (d0 + 1 < D_) { float4 v = dv[(size_t)(d0 + 1) * 32 + lane];
            dot1 = qv.x*v.x + qv.y*v.y + qv.z*v.z + qv.w*v.w;
            nr1  = v.x*v.x + v.y*v.y + v.z*v.z + v.w*v.w; }
        if (d0 + 2 < D_) { float4 v = dv[(size_t)(d0 + 2) * 32 + lane];
            dot2 = qv.x*v.x + qv.y*v.y + qv.z*v.z + qv.w*v.w;
            nr2  = v.x*v.x + v.y*v.y + v.z*v.z + v.w*v.w; }
        if (d0 + 3 < D_) { float4 v = dv[(size_t)(d0 + 3) * 32 + lane];
            dot3 = qv.x*v.x + qv.y*v.y + qv.z*v.z + qv.w*v.w;
            nr3  = v.x*v.x + v.y*v.y + v.z*v.z + v.w*v.w; }

        #pragma unroll
        for (int o = 16; o; o >>= 1) {
            dot0 += __shfl_xor_sync(0xFFFFFFFFu, dot0, o);
            nr0  += __shfl_xor_sync(0xFFFFFFFFu, nr0,  o);
            dot1 += __shfl_xor_sync(0xFFFFFFFFu, dot1, o);
            nr1  += __shfl_xor_sync(0xFFFFFFFFu, nr1,  o);
            dot2 += __shfl_xor_sync(0xFFFFFFFFu, dot2, o);
            nr2  += __shfl_xor_sync(0xFFFFFFFFu, nr2,  o);
            dot3 += __shfl_xor_sync(0xFFFFFFFFu, dot3, o);
            nr3  += __shfl_xor_sync(0xFFFFFFFFu, nr3,  o);
        }

        // 4 lanes handle the 4 docs' epilogues in parallel
        if (lane < 4) {
            int d = d0 + lane;
            if (d < D_) {
                float dt = (lane == 0) ? dot0 : (lane == 1) ? dot1 : (lane == 2) ? dot2 : dot3;
                float nr = (lane == 0) ? nr0  : (lane == 1) ? nr1  : (lane == 2) ? nr2  : nr3;
                float sim = dt / fmaxf(qn * sqrtf(nr), 1e-8f);
                float t   = (1.0f - sim) * invDelta;
                float mf  = floorf(t);
                int   m0  = (int)mf;
                float fr  = t - mf;
                float w0  = 1.0f - fr;
                int   lab = lb[d];
                if (m0 >= 0 && m0 < NBIN_) {
                    atomicAdd(&s_hall[m0], w0);
                    if (lab) atomicAdd(&s_hlab[m0], w0);
                }
                int m1 = m0 + 1;
                if (m1 >= 0 && m1 < NBIN_) {
                    atomicAdd(&s_hall[m1], fr);
                    if (lab) atomicAdd(&s_hlab[m1], fr);
                }
                labcnt += (float)lab;
            }
        }
    }

    // reduce label count within warp, stage per-warp
    #pragma unroll
    for (int o = 16; o; o >>= 1) labcnt += __shfl_xor_sync(0xFFFFFFFFu, labcnt, o);
    if (lane == 0) s_wlab[warp] = labcnt;
    __syncthreads();

    if (tid < NBIN_) {
        atomicAdd(&g_hall[b * NBIN_ + tid], s_hall[tid]);
        atomicAdd(&g_hlab[b * NBIN_ + tid], s_hlab[tid]);
    }
    if (tid == 0) {
        float s = 0.0f;
        #pragma unroll
        for (int w = 0; w < 8; w++) s += s_wlab[w];
        atomicAdd(&g_labsum[b], s);
    }
}

// ---------------- kernel 3: prefix sums + final scalar ----------------
__global__ void qap_finalize(float* __restrict__ out) {
    int t = threadIdx.x;
    float apq = 0.0f;
    if (t < B_) {
        float cl = 0.0f, ca = 0.0f;
        float inv_lab = 1.0f / g_labsum[t];
        float s = 0.0f;
        #pragma unroll
        for (int n = 0; n < NBIN_; n++) {
            float hl = g_hlab[t * NBIN_ + n];
            float ha = g_hall[t * NBIN_ + n];
            cl += hl;
            ca += ha;
            float prec = cl / (ca + 1e-16f);
            float rec  = hl * inv_lab;
            s += prec * rec;
        }
        apq = s / (float)NBIN_;
    }
    #pragma unroll
    for (int o = 16; o; o >>= 1) apq += __shfl_xor_sync(0xFFFFFFFFu, apq, o);
    if (t == 0) out[0] = apq / (float)B_;
}

extern "C" void kernel_launch(void* const* d_in, const int* in_sizes, int n_in,
                              void* d_out, int out_size) {
    const float* qX     = (const float*)d_in[0];
    const float* dXs    = (const float*)d_in[1];
    const int*   labels = (const int*)d_in[2];
    float*       out    = (float*)d_out;

    qap_init<<<1, 512>>>(qX);
    qap_accum<<<dim3(64, B_), 256>>>(qX, dXs, labels);
    qap_finalize<<<1, 32>>>(out);
}

// round 2
// speedup vs baseline: 1.2603x; 1.2603x over previous
#include <cuda_runtime.h>
#include <math.h>

#define B_    16
#define D_    100000
#define M_    128
#define NBIN_ 25
#define G_    27          // blocks per batch (grid.x)

// per-block partial results (no init kernel needed: plain stores, not atomics)
__device__ float g_hl[B_ * G_][NBIN_];
__device__ float g_ha[B_ * G_][NBIN_];
__device__ float g_ls[B_ * G_];

// ---------------- kernel 1: main accumulation (HBM-bound) ----------------
__global__ void __launch_bounds__(256, 3)
qap_accum(const float* __restrict__ qX,
          const float* __restrict__ dXs,
          const int*   __restrict__ labels) {
    const int b    = blockIdx.y;
    const int bx   = blockIdx.x;
    const int tid  = threadIdx.x;
    const int lane = tid & 31;
    const int warp = tid >> 5;
    const int e    = lane & 7;   // float4 slot within row
    const int g    = lane >> 3;  // row within quad (0..3)

    __shared__ float s_hl[NBIN_];
    __shared__ float s_ha[NBIN_];
    __shared__ float s_wl[8];

    if (tid < NBIN_) { s_hl[tid] = 0.0f; s_ha[tid] = 0.0f; }
    __syncthreads();

    // query vector slices for this lane's octet position
    const float4* __restrict__ qf = reinterpret_cast<const float4*>(qX + b * M_);
    const float4 q0 = qf[e], q1 = qf[e + 8], q2 = qf[e + 16], q3 = qf[e + 24];

    // |q|^2 via 8-lane group reduce (group spans e=0..7 exactly once)
    float qs = q0.x*q0.x + q0.y*q0.y + q0.z*q0.z + q0.w*q0.w
             + q1.x*q1.x + q1.y*q1.y + q1.z*q1.z + q1.w*q1.w
             + q2.x*q2.x + q2.y*q2.y + q2.z*q2.z + q2.w*q2.w
             + q3.x*q3.x + q3.y*q3.y + q3.z*q3.z + q3.w*q3.w;
    qs += __shfl_xor_sync(0xFFFFFFFFu, qs, 4);
    qs += __shfl_xor_sync(0xFFFFFFFFu, qs, 2);
    qs += __shfl_xor_sync(0xFFFFFFFFu, qs, 1);
    const float qn = sqrtf(qs);

    const float4* __restrict__ dv = reinterpret_cast<const float4*>(dXs + (size_t)b * D_ * M_);
    const int*    __restrict__ lb = labels + b * D_;

    const int wid     = bx * 8 + warp;
    const int stride8 = G_ * 8 * 8;   // docs advanced per sweep
    float labcnt = 0.0f;

    // D % 8 == 0, d0 is a multiple of 8 -> whole 8-doc chunk valid iff d0 < D
    for (int d0 = wid * 8; d0 < D_; d0 += stride8) {
        const float4* __restrict__ ra = dv + (size_t)(d0 + g) * 32;
        const float4* __restrict__ rb = ra + 4 * 32;

        // 8 front-batched 16B loads (4 KB per warp-iter, perfectly coalesced)
        const float4 a0 = ra[e], a1 = ra[e + 8], a2 = ra[e + 16], a3 = ra[e + 24];
        const float4 b0 = rb[e], b1 = rb[e + 8], b2 = rb[e + 16], b3 = rb[e + 24];

        float dota = q0.x*a0.x + q0.y*a0.y + q0.z*a0.z + q0.w*a0.w
                   + q1.x*a1.x + q1.y*a1.y + q1.z*a1.z + q1.w*a1.w
                   + q2.x*a2.x + q2.y*a2.y + q2.z*a2.z + q2.w*a2.w
                   + q3.x*a3.x + q3.y*a3.y + q3.z*a3.z + q3.w*a3.w;
        float nra  = a0.x*a0.x + a0.y*a0.y + a0.z*a0.z + a0.w*a0.w
                   + a1.x*a1.x + a1.y*a1.y + a1.z*a1.z + a1.w*a1.w
                   + a2.x*a2.x + a2.y*a2.y + a2.z*a2.z + a2.w*a2.w
                   + a3.x*a3.x + a3.y*a3.y + a3.z*a3.z + a3.w*a3.w;
        float dotb = q0.x*b0.x + q0.y*b0.y + q0.z*b0.z + q0.w*b0.w
                   + q1.x*b1.x + q1.y*b1.y + q1.z*b1.z + q1.w*b1.w
                   + q2.x*b2.x + q2.y*b2.y + q2.z*b2.z + q2.w*b2.w
                   + q3.x*b3.x + q3.y*b3.y + q3.z*b3.z + q3.w*b3.w;
        float nrb  = b0.x*b0.x + b0.y*b0.y + b0.z*b0.z + b0.w*b0.w
                   + b1.x*b1.x + b1.y*b1.y + b1.z*b1.z + b1.w*b1.w
                   + b2.x*b2.x + b2.y*b2.y + b2.z*b2.z + b2.w*b2.w
                   + b3.x*b3.x + b3.y*b3.y + b3.z*b3.z + b3.w*b3.w;

        // 3-round reduce within each 8-lane group
        #pragma unroll
        for (int o = 4; o; o >>= 1) {
            dota += __shfl_xor_sync(0xFFFFFFFFu, dota, o);
            nra  += __shfl_xor_sync(0xFFFFFFFFu, nra,  o);
            dotb += __shfl_xor_sync(0xFFFFFFFFu, dotb, o);
            nrb  += __shfl_xor_sync(0xFFFFFFFFu, nrb,  o);
        }

        // 8 handler lanes: p==0 -> doc d0+g, p==1 -> doc d0+4+g
        const int p = lane & 7;
        if (p < 2) {
            const int d   = d0 + g + (p << 2);
            const float dt = p ? dotb : dota;
            const float nr = p ? nrb  : nra;
            const float sim = dt / fmaxf(qn * sqrtf(nr), 1e-8f);
            const float t   = (1.0f - sim) * 12.0f;   // /DELTA
            const float mf  = floorf(t);
            const int   m0  = (int)mf;
            const float fr  = t - mf;
            const int   lab = lb[d];
            if (m0 >= 0 && m0 < NBIN_) {
                atomicAdd(&s_ha[m0], 1.0f - fr);
                if (lab) atomicAdd(&s_hl[m0], 1.0f - fr);
            }
            const int m1 = m0 + 1;
            if (m1 >= 0 && m1 < NBIN_) {
                atomicAdd(&s_ha[m1], fr);
                if (lab) atomicAdd(&s_hl[m1], fr);
            }
            labcnt += (float)lab;
        }
    }

    // label-count: full warp reduce, stage per warp
    #pragma unroll
    for (int o = 16; o; o >>= 1) labcnt += __shfl_xor_sync(0xFFFFFFFFu, labcnt, o);
    if (lane == 0) s_wl[warp] = labcnt;
    __syncthreads();

    const int slot = b * G_ + bx;
    if (tid < NBIN_) { g_hl[slot][tid] = s_hl[tid]; g_ha[slot][tid] = s_ha[tid]; }
    if (tid == 0) {
        float s = 0.0f;
        #pragma unroll
        for (int w = 0; w < 8; w++) s += s_wl[w];
        g_ls[slot] = s;
    }
}

// ---------------- kernel 2: combine partials + prefix sums + scalar ----------------
__global__ void qap_finalize(float* __restrict__ out) {
    __shared__ float hl[B_][NBIN_];
    __shared__ float ha[B_][NBIN_];
    __shared__ float ls[B_];
    const int t = threadIdx.x;

    if (t < B_ * NBIN_) {
        const int b = t / NBIN_, n = t % NBIN_;
        float shl = 0.0f, sha = 0.0f;
        #pragma unroll
        for (int j = 0; j < G_; j++) {
            shl += g_hl[b * G_ + j][n];
            sha += g_ha[b * G_ + j][n];
        }
        hl[b][n] = shl;
        ha[b][n] = sha;
    }
    if (t < B_) {
        float s = 0.0f;
        #pragma unroll
        for (int j = 0; j < G_; j++) s += g_ls[t * G_ + j];
        ls[t] = s;
    }
    __syncthreads();

    float apq = 0.0f;
    if (t < B_) {
        float cl = 0.0f, ca = 0.0f, s = 0.0f;
        const float inv_lab = 1.0f / ls[t];
        #pragma unroll
        for (int n = 0; n < NBIN_; n++) {
            const float vhl = hl[t][n];
            cl += vhl;
            ca += ha[t][n];
            s += (cl / (ca + 1e-16f)) * (vhl * inv_lab);
        }
        apq = s / (float)NBIN_;
    }
    if (t < 32) {
        #pragma unroll
        for (int o = 16; o; o >>= 1) apq += __shfl_xor_sync(0xFFFFFFFFu, apq, o);
        if (t == 0) out[0] = apq / (float)B_;
    }
}

extern "C" void kernel_launch(void* const* d_in, const int* in_sizes, int n_in,
                              void* d_out, int out_size) {
    const float* qX     = (const float*)d_in[0];
    const float* dXs    = (const float*)d_in[1];
    const int*   labels = (const int*)d_in[2];
    float*       out    = (float*)d_out;

    qap_accum<<<dim3(G_, B_), 256>>>(qX, dXs, labels);
    qap_finalize<<<1, 512>>>(out);
}

// round 3
// speedup vs baseline: 1.2620x; 1.0014x over previous
#include <cuda_runtime.h>
#include <math.h>

#define B_    16
#define D_    100000
#define M_    128
#define NBIN_ 25
#define G_    27                  // blocks per batch
#define TOTAL_ (B_ * G_)          // 432 blocks

// global accumulators — zero at module load; last block re-zeros them each
// run so every graph replay starts from identical state.
__device__ float    g_hla[B_][NBIN_];   // sum over all docs
__device__ float    g_hll[B_][NBIN_];   // sum over positive docs
__device__ float    g_lsum[B_];         // label counts
__device__ unsigned g_ticket;

__global__ void __launch_bounds__(256, 3)
qap_fused(const float* __restrict__ qX,
          const float* __restrict__ dXs,
          const int*   __restrict__ labels,
          float*       __restrict__ out) {
    const int b    = blockIdx.y;
    const int tid  = threadIdx.x;
    const int lane = tid & 31;
    const int warp = tid >> 5;
    const int e    = lane & 7;   // float4 slot within row
    const int g    = lane >> 3;  // row within quad (0..3)

    __shared__ float s_hl[NBIN_];
    __shared__ float s_ha[NBIN_];
    __shared__ float s_wl[8];
    __shared__ int   s_last;

    if (tid < NBIN_) { s_hl[tid] = 0.0f; s_ha[tid] = 0.0f; }
    __syncthreads();

    // query slices + |q| via 8-lane group reduce
    const float4* __restrict__ qf = reinterpret_cast<const float4*>(qX + b * M_);
    const float4 q0 = qf[e], q1 = qf[e + 8], q2 = qf[e + 16], q3 = qf[e + 24];
    float qs = q0.x*q0.x + q0.y*q0.y + q0.z*q0.z + q0.w*q0.w
             + q1.x*q1.x + q1.y*q1.y + q1.z*q1.z + q1.w*q1.w
             + q2.x*q2.x + q2.y*q2.y + q2.z*q2.z + q2.w*q2.w
             + q3.x*q3.x + q3.y*q3.y + q3.z*q3.z + q3.w*q3.w;
    qs += __shfl_xor_sync(0xFFFFFFFFu, qs, 4);
    qs += __shfl_xor_sync(0xFFFFFFFFu, qs, 2);
    qs += __shfl_xor_sync(0xFFFFFFFFu, qs, 1);
    const float qn = sqrtf(qs);

    const float4* __restrict__ dv = reinterpret_cast<const float4*>(dXs + (size_t)b * D_ * M_);
    const int*    __restrict__ lb = labels + b * D_;

    const int wid     = blockIdx.x * 8 + warp;
    const int stride8 = G_ * 8 * 8;
    float labcnt = 0.0f;

    for (int d0 = wid * 8; d0 < D_; d0 += stride8) {
        const float4* __restrict__ ra = dv + (size_t)(d0 + g) * 32;
        const float4* __restrict__ rb = ra + 4 * 32;

        const float4 a0 = ra[e], a1 = ra[e + 8], a2 = ra[e + 16], a3 = ra[e + 24];
        const float4 b0 = rb[e], b1 = rb[e + 8], b2 = rb[e + 16], b3 = rb[e + 24];

        float dota = q0.x*a0.x + q0.y*a0.y + q0.z*a0.z + q0.w*a0.w
                   + q1.x*a1.x + q1.y*a1.y + q1.z*a1.z + q1.w*a1.w
                   + q2.x*a2.x + q2.y*a2.y + q2.z*a2.z + q2.w*a2.w
                   + q3.x*a3.x + q3.y*a3.y + q3.z*a3.z + q3.w*a3.w;
        float nra  = a0.x*a0.x + a0.y*a0.y + a0.z*a0.z + a0.w*a0.w
                   + a1.x*a1.x + a1.y*a1.y + a1.z*a1.z + a1.w*a1.w
                   + a2.x*a2.x + a2.y*a2.y + a2.z*a2.z + a2.w*a2.w
                   + a3.x*a3.x + a3.y*a3.y + a3.z*a3.z + a3.w*a3.w;
        float dotb = q0.x*b0.x + q0.y*b0.y + q0.z*b0.z + q0.w*b0.w
                   + q1.x*b1.x + q1.y*b1.y + q1.z*b1.z + q1.w*b1.w
                   + q2.x*b2.x + q2.y*b2.y + q2.z*b2.z + q2.w*b2.w
                   + q3.x*b3.x + q3.y*b3.y + q3.z*b3.z + q3.w*b3.w;
        float nrb  = b0.x*b0.x + b0.y*b0.y + b0.z*b0.z + b0.w*b0.w
                   + b1.x*b1.x + b1.y*b1.y + b1.z*b1.z + b1.w*b1.w
                   + b2.x*b2.x + b2.y*b2.y + b2.z*b2.z + b2.w*b2.w
                   + b3.x*b3.x + b3.y*b3.y + b3.z*b3.z + b3.w*b3.w;

        #pragma unroll
        for (int o = 4; o; o >>= 1) {
            dota += __shfl_xor_sync(0xFFFFFFFFu, dota, o);
            nra  += __shfl_xor_sync(0xFFFFFFFFu, nra,  o);
            dotb += __shfl_xor_sync(0xFFFFFFFFu, dotb, o);
            nrb  += __shfl_xor_sync(0xFFFFFFFFu, nrb,  o);
        }

        const int p = lane & 7;
        if (p < 2) {
            const int d    = d0 + g + (p << 2);
            const float dt = p ? dotb : dota;
            const float nr = p ? nrb  : nra;
            const float sim = dt / fmaxf(qn * sqrtf(nr), 1e-8f);
            const float t   = (1.0f - sim) * 12.0f;
            const float mf  = floorf(t);
            const int   m0  = (int)mf;
            const float fr  = t - mf;
            const int   lab = lb[d];
            if (m0 >= 0 && m0 < NBIN_) {
                atomicAdd(&s_ha[m0], 1.0f - fr);
                if (lab) atomicAdd(&s_hl[m0], 1.0f - fr);
            }
            const int m1 = m0 + 1;
            if (m1 >= 0 && m1 < NBIN_) {
                atomicAdd(&s_ha[m1], fr);
                if (lab) atomicAdd(&s_hl[m1], fr);
            }
            labcnt += (float)lab;
        }
    }

    #pragma unroll
    for (int o = 16; o; o >>= 1) labcnt += __shfl_xor_sync(0xFFFFFFFFu, labcnt, o);
    if (lane == 0) s_wl[warp] = labcnt;
    __syncthreads();

    // flush block partials to global accumulators
    if (tid < NBIN_) {
        atomicAdd(&g_hla[b][tid], s_ha[tid]);
        atomicAdd(&g_hll[b][tid], s_hl[tid]);
    }
    if (tid == 0) {
        float s = 0.0f;
        #pragma unroll
        for (int w = 0; w < 8; w++) s += s_wl[w];
        atomicAdd(&g_lsum[b], s);
    }

    // grid completion ticket (threadFenceReduction pattern)
    __threadfence();
    __syncthreads();
    if (tid == 0) {
        unsigned prev = atomicAdd(&g_ticket, 1u);
        s_last = (prev == TOTAL_ - 1u);
    }
    __syncthreads();
    if (!s_last) return;

    // ---------------- last block: finalize + reset state ----------------
    __shared__ float f_hl[B_][NBIN_];
    __shared__ float f_ha[B_][NBIN_];
    __shared__ float f_ls[B_];

    for (int idx = tid; idx < B_ * NBIN_; idx += 256) {
        const int bb = idx / NBIN_, n = idx % NBIN_;
        f_hl[bb][n] = __ldcg(&g_hll[bb][n]);
        f_ha[bb][n] = __ldcg(&g_hla[bb][n]);
        g_hll[bb][n] = 0.0f;            // reset for next replay
        g_hla[bb][n] = 0.0f;
    }
    if (tid < B_) {
        f_ls[tid] = __ldcg(&g_lsum[tid]);
        g_lsum[tid] = 0.0f;
    }
    __syncthreads();

    float apq = 0.0f;
    if (tid < B_) {
        float cl = 0.0f, ca = 0.0f, s = 0.0f;
        const float inv_lab = 1.0f / f_ls[tid];
        #pragma unroll
        for (int n = 0; n < NBIN_; n++) {
            const float vhl = f_hl[tid][n];
            cl += vhl;
            ca += f_ha[tid][n];
            s += (cl / (ca + 1e-16f)) * (vhl * inv_lab);
        }
        apq = s / (float)NBIN_;
    }
    if (tid < 32) {
        #pragma unroll
        for (int o = 16; o; o >>= 1) apq += __shfl_xor_sync(0xFFFFFFFFu, apq, o);
        if (tid == 0) {
            out[0] = apq / (float)B_;
            g_ticket = 0u;              // reset ticket for next replay
        }
    }
}

extern "C" void kernel_launch(void* const* d_in, const int* in_sizes, int n_in,
                              void* d_out, int out_size) {
    const float* qX     = (const float*)d_in[0];
    const float* dXs    = (const float*)d_in[1];
    const int*   labels = (const int*)d_in[2];
    float*       out    = (float*)d_out;

    qap_fused<<<dim3(G_, B_), 256>>>(qX, dXs, labels, out);
}

// round 5
// speedup vs baseline: 1.2983x; 1.0288x over previous
#include <cuda_runtime.h>
#include <math.h>

#define B_    16
#define D_    100000
#define M_    128
#define NBIN_ 25
#define G_    37                  // blocks per batch -> 592 total = 4/SM exactly
#define TOTAL_ (B_ * G_)

// global accumulators — zero at module load; last block re-zeros them each
// run so every graph replay starts from identical state.
__device__ float    g_hla[B_][NBIN_];
__device__ float    g_hll[B_][NBIN_];
__device__ float    g_lsum[B_];
__device__ unsigned g_ticket;

__global__ void __launch_bounds__(256, 4)
qap_fused(const float* __restrict__ qX,
          const float* __restrict__ dXs,
          const int*   __restrict__ labels,
          float*       __restrict__ out) {
    const int b    = blockIdx.y;
    const int tid  = threadIdx.x;
    const int lane = tid & 31;
    const int warp = tid >> 5;
    const int e    = lane & 7;   // float4 slot within row
    const int g    = lane >> 3;  // doc within quad (0..3)

    __shared__ float s_hl[NBIN_];
    __shared__ float s_ha[NBIN_];
    __shared__ float s_wl[8];
    __shared__ int   s_last;

    if (tid < NBIN_) { s_hl[tid] = 0.0f; s_ha[tid] = 0.0f; }
    __syncthreads();

    // query slices + 1/|q| via 8-lane group butterfly
    const float4* __restrict__ qf = reinterpret_cast<const float4*>(qX + b * M_);
    const float4 q0 = qf[e], q1 = qf[e + 8], q2 = qf[e + 16], q3 = qf[e + 24];
    float qs = q0.x*q0.x + q0.y*q0.y + q0.z*q0.z + q0.w*q0.w
             + q1.x*q1.x + q1.y*q1.y + q1.z*q1.z + q1.w*q1.w
             + q2.x*q2.x + q2.y*q2.y + q2.z*q2.z + q2.w*q2.w
             + q3.x*q3.x + q3.y*q3.y + q3.z*q3.z + q3.w*q3.w;
    qs += __shfl_xor_sync(0xFFFFFFFFu, qs, 4);
    qs += __shfl_xor_sync(0xFFFFFFFFu, qs, 2);
    qs += __shfl_xor_sync(0xFFFFFFFFu, qs, 1);
    const float inv_qn = rsqrtf(qs);

    const float4* __restrict__ dv = reinterpret_cast<const float4*>(dXs + (size_t)b * D_ * M_);
    const int*    __restrict__ lb = labels + b * D_;

    const int wid     = blockIdx.x * 8 + warp;
    const int stride8 = G_ * 8 * 8;
    float labcnt = 0.0f;

    for (int d0 = wid * 8; d0 < D_; d0 += stride8) {
        const float4* __restrict__ ra = dv + (size_t)(d0 + g) * 32;
        const float4* __restrict__ rb = ra + 4 * 32;

        // 8 front-batched streaming 16B loads (4 KB per warp-iter)
        const float4 a0 = __ldcs(ra + e),      a1 = __ldcs(ra + e + 8);
        const float4 a2 = __ldcs(ra + e + 16), a3 = __ldcs(ra + e + 24);
        const float4 b0 = __ldcs(rb + e),      b1 = __ldcs(rb + e + 8);
        const float4 b2 = __ldcs(rb + e + 16), b3 = __ldcs(rb + e + 24);

        float dota = q0.x*a0.x + q0.y*a0.y + q0.z*a0.z + q0.w*a0.w
                   + q1.x*a1.x + q1.y*a1.y + q1.z*a1.z + q1.w*a1.w
                   + q2.x*a2.x + q2.y*a2.y + q2.z*a2.z + q2.w*a2.w
                   + q3.x*a3.x + q3.y*a3.y + q3.z*a3.z + q3.w*a3.w;
        float nra  = a0.x*a0.x + a0.y*a0.y + a0.z*a0.z + a0.w*a0.w
                   + a1.x*a1.x + a1.y*a1.y + a1.z*a1.z + a1.w*a1.w
                   + a2.x*a2.x + a2.y*a2.y + a2.z*a2.z + a2.w*a2.w
                   + a3.x*a3.x + a3.y*a3.y + a3.z*a3.z + a3.w*a3.w;
        float dotb = q0.x*b0.x + q0.y*b0.y + q0.z*b0.z + q0.w*b0.w
                   + q1.x*b1.x + q1.y*b1.y + q1.z*b1.z + q1.w*b1.w
                   + q2.x*b2.x + q2.y*b2.y + q2.z*b2.z + q2.w*b2.w
                   + q3.x*b3.x + q3.y*b3.y + q3.z*b3.z + q3.w*b3.w;
        float nrb  = b0.x*b0.x + b0.y*b0.y + b0.z*b0.z + b0.w*b0.w
                   + b1.x*b1.x + b1.y*b1.y + b1.z*b1.z + b1.w*b1.w
                   + b2.x*b2.x + b2.y*b2.y + b2.z*b2.z + b2.w*b2.w
                   + b3.x*b3.x + b3.y*b3.y + b3.z*b3.z + b3.w*b3.w;

        // 3-round 8-lane group butterfly (4 independent values pipeline)
        #pragma unroll
        for (int o = 4; o; o >>= 1) {
            dota += __shfl_xor_sync(0xFFFFFFFFu, dota, o);
            nra  += __shfl_xor_sync(0xFFFFFFFFu, nra,  o);
            dotb += __shfl_xor_sync(0xFFFFFFFFu, dotb, o);
            nrb  += __shfl_xor_sync(0xFFFFFFFFu, nrb,  o);
        }

        const int p = lane & 7;
        if (p < 2) {
            const int d    = d0 + g + (p << 2);
            const float dt = p ? dotb : dota;
            const float nr = p ? nrb  : nra;
            const float sim = dt * rsqrtf(nr) * inv_qn;   // eps never binds (norms ~11)
            const float t   = (1.0f - sim) * 12.0f;
            const float mf  = floorf(t);
            const int   m0  = (int)mf;
            const float fr  = t - mf;
            const int   lab = lb[d];
            if (m0 >= 0 && m0 < NBIN_) {
                atomicAdd(&s_ha[m0], 1.0f - fr);
                if (lab) atomicAdd(&s_hl[m0], 1.0f - fr);
            }
            const int m1 = m0 + 1;
            if (m1 >= 0 && m1 < NBIN_) {
                atomicAdd(&s_ha[m1], fr);
                if (lab) atomicAdd(&s_hl[m1], fr);
            }
            labcnt += (float)lab;
        }
    }

    #pragma unroll
    for (int o = 16; o; o >>= 1) labcnt += __shfl_xor_sync(0xFFFFFFFFu, labcnt, o);
    if (lane == 0) s_wl[warp] = labcnt;
    __syncthreads();

    if (tid < NBIN_) {
        atomicAdd(&g_hla[b][tid], s_ha[tid]);
        atomicAdd(&g_hll[b][tid], s_hl[tid]);
    }
    if (tid == 0) {
        float s = 0.0f;
        #pragma unroll
        for (int w = 0; w < 8; w++) s += s_wl[w];
        atomicAdd(&g_lsum[b], s);
    }

    __threadfence();
    __syncthreads();
    if (tid == 0) {
        unsigned prev = atomicAdd(&g_ticket, 1u);
        s_last = (prev == TOTAL_ - 1u);
    }
    __syncthreads();
    if (!s_last) return;

    // ---------------- last block: finalize + reset state ----------------
    __shared__ float f_hl[B_][NBIN_];
    __shared__ float f_ha[B_][NBIN_];
    __shared__ float f_ls[B_];

    for (int idx = tid; idx < B_ * NBIN_; idx += 256) {
        const int bb = idx / NBIN_, n = idx % NBIN_;
        f_hl[bb][n] = __ldcg(&g_hll[bb][n]);
        f_ha[bb][n] = __ldcg(&g_hla[bb][n]);
        g_hll[bb][n] = 0.0f;
        g_hla[bb][n] = 0.0f;
    }
    if (tid < B_) {
        f_ls[tid] = __ldcg(&g_lsum[tid]);
        g_lsum[tid] = 0.0f;
    }
    __syncthreads();

    float apq = 0.0f;
    if (tid < B_) {
        float cl = 0.0f, ca = 0.0f, s = 0.0f;
        const float inv_lab = 1.0f / f_ls[tid];
        #pragma unroll
        for (int n = 0; n < NBIN_; n++) {
            const float vhl = f_hl[tid][n];
            cl += vhl;
            ca += f_ha[tid][n];
            s += (cl / (ca + 1e-16f)) * (vhl * inv_lab);
        }
        apq = s / (float)NBIN_;
    }
    if (tid < 32) {
        #pragma unroll
        for (int o = 16; o; o >>= 1) apq += __shfl_xor_sync(0xFFFFFFFFu, apq, o);
        if (tid == 0) {
            out[0] = apq / (float)B_;
            g_ticket = 0u;
        }
    }
}

extern "C" void kernel_launch(void* const* d_in, const int* in_sizes, int n_in,
                              void* d_out, int out_size) {
    const float* qX     = (const float*)d_in[0];
    const float* dXs    = (const float*)d_in[1];
    const int*   labels = (const int*)d_in[2];
    float*       out    = (float*)d_out;

    qap_fused<<<dim3(G_, B_), 256>>>(qX, dXs, labels, out);
}

// round 6
// speedup vs baseline: 1.4083x; 1.0847x over previous
#include <cuda_runtime.h>
#include <math.h>

#define B_    16
#define D_    100000
#define M_    128
#define NBIN_ 25
#define G_    37                  // blocks per batch -> 592 total = 4/SM exactly
#define TOTAL_ (B_ * G_)

// global accumulators — zero at module load; last block re-zeros them each
// run so every graph replay starts from identical state.
__device__ float    g_hla[B_][NBIN_];
__device__ float    g_hll[B_][NBIN_];
__device__ float    g_lsum[B_];
__device__ unsigned g_ticket;

__global__ void __launch_bounds__(256, 4)
qap_fused(const float* __restrict__ qX,
          const float* __restrict__ dXs,
          const int*   __restrict__ labels,
          float*       __restrict__ out) {
    const int b    = blockIdx.y;
    const int tid  = threadIdx.x;
    const int lane = tid & 31;
    const int warp = tid >> 5;
    const int e    = lane & 7;   // position within 8-lane group
    const int g    = lane >> 3;  // group index (0..3)

    __shared__ float s_hl[NBIN_];
    __shared__ float s_ha[NBIN_];
    __shared__ float s_wl[8];
    __shared__ int   s_last;

    if (tid < NBIN_) { s_hl[tid] = 0.0f; s_ha[tid] = 0.0f; }
    __syncthreads();

    // query slices + 1/|q| via 8-lane group butterfly
    const float4* __restrict__ qf = reinterpret_cast<const float4*>(qX + b * M_);
    const float4 q0 = qf[e], q1 = qf[e + 8], q2 = qf[e + 16], q3 = qf[e + 24];
    float qs = q0.x*q0.x + q0.y*q0.y + q0.z*q0.z + q0.w*q0.w
             + q1.x*q1.x + q1.y*q1.y + q1.z*q1.z + q1.w*q1.w
             + q2.x*q2.x + q2.y*q2.y + q2.z*q2.z + q2.w*q2.w
             + q3.x*q3.x + q3.y*q3.y + q3.z*q3.z + q3.w*q3.w;
    qs += __shfl_xor_sync(0xFFFFFFFFu, qs, 4);
    qs += __shfl_xor_sync(0xFFFFFFFFu, qs, 2);
    qs += __shfl_xor_sync(0xFFFFFFFFu, qs, 1);
    const float inv_qn = rsqrtf(qs);

    const float4* __restrict__ dv = reinterpret_cast<const float4*>(dXs + (size_t)b * D_ * M_);
    const int*    __restrict__ lb = labels + b * D_;

    const int wid     = blockIdx.x * 8 + warp;
    const int stride8 = G_ * 8 * 8;
    // this lane's epilogue doc offset within the 8-doc chunk:
    // e<4 -> doc a (d0+g), e>=4 -> doc b (d0+4+g)
    const int docoff  = g + (e & 4);
    const int role    = e & 3;          // 0: ha[m0], 1: ha[m1], 2: hl[m0], 3: hl[m1]
    float labcnt = 0.0f;

    for (int d0 = wid * 8; d0 < D_; d0 += stride8) {
        const float4* __restrict__ ra = dv + (size_t)(d0 + g) * 32;
        const float4* __restrict__ rb = ra + 4 * 32;

        // front-batched loads: 8x16B vector + this lane's label (hidden latency)
        const float4 a0 = __ldcs(ra + e),      a1 = __ldcs(ra + e + 8);
        const float4 a2 = __ldcs(ra + e + 16), a3 = __ldcs(ra + e + 24);
        const float4 b0 = __ldcs(rb + e),      b1 = __ldcs(rb + e + 8);
        const float4 b2 = __ldcs(rb + e + 16), b3 = __ldcs(rb + e + 24);
        const int    lab = lb[d0 + docoff];

        float dota = q0.x*a0.x + q0.y*a0.y + q0.z*a0.z + q0.w*a0.w
                   + q1.x*a1.x + q1.y*a1.y + q1.z*a1.z + q1.w*a1.w
                   + q2.x*a2.x + q2.y*a2.y + q2.z*a2.z + q2.w*a2.w
                   + q3.x*a3.x + q3.y*a3.y + q3.z*a3.z + q3.w*a3.w;
        float nra  = a0.x*a0.x + a0.y*a0.y + a0.z*a0.z + a0.w*a0.w
                   + a1.x*a1.x + a1.y*a1.y + a1.z*a1.z + a1.w*a1.w
                   + a2.x*a2.x + a2.y*a2.y + a2.z*a2.z + a2.w*a2.w
                   + a3.x*a3.x + a3.y*a3.y + a3.z*a3.z + a3.w*a3.w;
        float dotb = q0.x*b0.x + q0.y*b0.y + q0.z*b0.z + q0.w*b0.w
                   + q1.x*b1.x + q1.y*b1.y + q1.z*b1.z + q1.w*b1.w
                   + q2.x*b2.x + q2.y*b2.y + q2.z*b2.z + q2.w*b2.w
                   + q3.x*b3.x + q3.y*b3.y + q3.z*b3.z + q3.w*b3.w;
        float nrb  = b0.x*b0.x + b0.y*b0.y + b0.z*b0.z + b0.w*b0.w
                   + b1.x*b1.x + b1.y*b1.y + b1.z*b1.z + b1.w*b1.w
                   + b2.x*b2.x + b2.y*b2.y + b2.z*b2.z + b2.w*b2.w
                   + b3.x*b3.x + b3.y*b3.y + b3.z*b3.z + b3.w*b3.w;

        // 3-round 8-lane group butterfly — afterwards ALL lanes hold the sums
        #pragma unroll
        for (int o = 4; o; o >>= 1) {
            dota += __shfl_xor_sync(0xFFFFFFFFu, dota, o);
            nra  += __shfl_xor_sync(0xFFFFFFFFu, nra,  o);
            dotb += __shfl_xor_sync(0xFFFFFFFFu, dotb, o);
            nrb  += __shfl_xor_sync(0xFFFFFFFFu, nrb,  o);
        }

        // all-lane epilogue: each lane performs exactly one histogram update
        const float dt  = (e < 4) ? dota : dotb;
        const float nr  = (e < 4) ? nra  : nrb;
        const float sim = dt * rsqrtf(nr) * inv_qn;   // eps never binds (norms ~11)
        const float t   = (1.0f - sim) * 12.0f;
        const float mf  = floorf(t);
        const int   m0  = (int)mf;
        const float fr  = t - mf;
        const int   m   = (role & 1) ? (m0 + 1) : m0;
        const float w   = (role & 1) ? fr : (1.0f - fr);
        float* dst      = (role & 2) ? s_hl : s_ha;
        const bool doit = (m >= 0) && (m < NBIN_) && (!(role & 2) || lab);
        if (doit) atomicAdd(dst + m, w);
        if (role == 0) labcnt += (float)lab;   // each doc counted once (e==0, e==4)
    }

    #pragma unroll
    for (int o = 16; o; o >>= 1) labcnt += __shfl_xor_sync(0xFFFFFFFFu, labcnt, o);
    if (lane == 0) s_wl[warp] = labcnt;
    __syncthreads();

    if (tid < NBIN_) {
        atomicAdd(&g_hla[b][tid], s_ha[tid]);
        atomicAdd(&g_hll[b][tid], s_hl[tid]);
    }
    if (tid == 0) {
        float s = 0.0f;
        #pragma unroll
        for (int w = 0; w < 8; w++) s += s_wl[w];
        atomicAdd(&g_lsum[b], s);
    }

    __threadfence();
    __syncthreads();
    if (tid == 0) {
        unsigned prev = atomicAdd(&g_ticket, 1u);
        s_last = (prev == TOTAL_ - 1u);
    }
    __syncthreads();
    if (!s_last) return;

    // ---------------- last block: finalize + reset state ----------------
    __shared__ float f_hl[B_][NBIN_];
    __shared__ float f_ha[B_][NBIN_];
    __shared__ float f_ls[B_];

    for (int idx = tid; idx < B_ * NBIN_; idx += 256) {
        const int bb = idx / NBIN_, n = idx % NBIN_;
        f_hl[bb][n] = __ldcg(&g_hll[bb][n]);
        f_ha[bb][n] = __ldcg(&g_hla[bb][n]);
        g_hll[bb][n] = 0.0f;
        g_hla[bb][n] = 0.0f;
    }
    if (tid < B_) {
        f_ls[tid] = __ldcg(&g_lsum[tid]);
        g_lsum[tid] = 0.0f;
    }
    __syncthreads();

    float apq = 0.0f;
    if (tid < B_) {
        float cl = 0.0f, ca = 0.0f, s = 0.0f;
        const float inv_lab = 1.0f / f_ls[tid];
        #pragma unroll
        for (int n = 0; n < NBIN_; n++) {
            const float vhl = f_hl[tid][n];
            cl += vhl;
            ca += f_ha[tid][n];
            s += (cl / (ca + 1e-16f)) * (vhl * inv_lab);
        }
        apq = s / (float)NBIN_;
    }
    if (tid < 32) {
        #pragma unroll
        for (int o = 16; o; o >>= 1) apq += __shfl_xor_sync(0xFFFFFFFFu, apq, o);
        if (tid == 0) {
            out[0] = apq / (float)B_;
            g_ticket = 0u;
        }
    }
}

extern "C" void kernel_launch(void* const* d_in, const int* in_sizes, int n_in,
                              void* d_out, int out_size) {
    const float* qX     = (const float*)d_in[0];
    const float* dXs    = (const float*)d_in[1];
    const int*   labels = (const int*)d_in[2];
    float*       out    = (float*)d_out;

    qap_fused<<<dim3(G_, B_), 256>>>(qX, dXs, labels, out);
}

// round 7
// speedup vs baseline: 1.4148x; 1.0046x over previous
#include <cuda_runtime.h>
#include <math.h>

#define B_    16
#define D_    100000
#define M_    128
#define NBIN_ 25
#define G_    37                  // blocks per batch -> 592 total = 4/SM exactly
#define TOTAL_ (B_ * G_)
#define NSLOT_ 27                 // padded: slot j == bin j-1; slots 0 and 26 are trash

// global accumulators — zero at module load; last block re-zeros them each
// run so every graph replay starts from identical state.
__device__ float    g_hla[B_][NBIN_];
__device__ float    g_hll[B_][NBIN_];
__device__ float    g_lsum[B_];
__device__ unsigned g_ticket;

__global__ void __launch_bounds__(256, 4)
qap_fused(const float* __restrict__ qX,
          const float* __restrict__ dXs,
          const int*   __restrict__ labels,
          float*       __restrict__ out) {
    const int b    = blockIdx.y;
    const int tid  = threadIdx.x;
    const int lane = tid & 31;
    const int warp = tid >> 5;
    const int e    = lane & 7;   // position within 8-lane group
    const int g    = lane >> 3;  // group index (0..3)

    // per-(warp,doc) private histograms: [warp][doc][arr][NSLOT_]
    __shared__ float s_hist[8 * 8 * 2 * NSLOT_];   // 3456 floats = 13.5 KB
    __shared__ float s_wl[8];
    __shared__ int   s_last;

    #pragma unroll
    for (int i = tid; i < 8 * 8 * 2 * NSLOT_; i += 256) s_hist[i] = 0.0f;
    __syncthreads();

    // query slices + 1/|q| via 8-lane group butterfly
    const float4* __restrict__ qf = reinterpret_cast<const float4*>(qX + b * M_);
    const float4 q0 = qf[e], q1 = qf[e + 8], q2 = qf[e + 16], q3 = qf[e + 24];
    float qs = q0.x*q0.x + q0.y*q0.y + q0.z*q0.z + q0.w*q0.w
             + q1.x*q1.x + q1.y*q1.y + q1.z*q1.z + q1.w*q1.w
             + q2.x*q2.x + q2.y*q2.y + q2.z*q2.z + q2.w*q2.w
             + q3.x*q3.x + q3.y*q3.y + q3.z*q3.z + q3.w*q3.w;
    qs += __shfl_xor_sync(0xFFFFFFFFu, qs, 4);
    qs += __shfl_xor_sync(0xFFFFFFFFu, qs, 2);
    qs += __shfl_xor_sync(0xFFFFFFFFu, qs, 1);
    const float inv_qn = rsqrtf(qs);

    const float4* __restrict__ dv = reinterpret_cast<const float4*>(dXs + (size_t)b * D_ * M_);
    const int*    __restrict__ lb = labels + b * D_;

    const int wid     = blockIdx.x * 8 + warp;
    const int stride8 = G_ * 8 * 8;
    const int docoff  = g + (e & 4);     // this lane's doc within the 8-doc chunk
    const int role    = e & 3;           // 0: ha[m0], 1: ha[m1], 2: hl[m0], 3: hl[m1]
    // lane's fixed base into its private histogram copy (+1 for m0=-1 padding)
    float* const hbase = s_hist + ((warp * 8 + docoff) * 2 + (role >> 1)) * NSLOT_
                       + (role & 1) + 1;
    float labcnt = 0.0f;

    for (int d0 = wid * 8; d0 < D_; d0 += stride8) {
        const float4* __restrict__ ra = dv + (size_t)(d0 + g) * 32;
        const float4* __restrict__ rb = ra + 4 * 32;

        // front-batched loads: 8x16B vector + this lane's label (latency hidden)
        const float4 a0 = __ldcs(ra + e),      a1 = __ldcs(ra + e + 8);
        const float4 a2 = __ldcs(ra + e + 16), a3 = __ldcs(ra + e + 24);
        const float4 b0 = __ldcs(rb + e),      b1 = __ldcs(rb + e + 8);
        const float4 b2 = __ldcs(rb + e + 16), b3 = __ldcs(rb + e + 24);
        const int    lab = lb[d0 + docoff];

        float dota = q0.x*a0.x + q0.y*a0.y + q0.z*a0.z + q0.w*a0.w
                   + q1.x*a1.x + q1.y*a1.y + q1.z*a1.z + q1.w*a1.w
                   + q2.x*a2.x + q2.y*a2.y + q2.z*a2.z + q2.w*a2.w
                   + q3.x*a3.x + q3.y*a3.y + q3.z*a3.z + q3.w*a3.w;
        float nra  = a0.x*a0.x + a0.y*a0.y + a0.z*a0.z + a0.w*a0.w
                   + a1.x*a1.x + a1.y*a1.y + a1.z*a1.z + a1.w*a1.w
                   + a2.x*a2.x + a2.y*a2.y + a2.z*a2.z + a2.w*a2.w
                   + a3.x*a3.x + a3.y*a3.y + a3.z*a3.z + a3.w*a3.w;
        float dotb = q0.x*b0.x + q0.y*b0.y + q0.z*b0.z + q0.w*b0.w
                   + q1.x*b1.x + q1.y*b1.y + q1.z*b1.z + q1.w*b1.w
                   + q2.x*b2.x + q2.y*b2.y + q2.z*b2.z + q2.w*b2.w
                   + q3.x*b3.x + q3.y*b3.y + q3.z*b3.z + q3.w*b3.w;
        float nrb  = b0.x*b0.x + b0.y*b0.y + b0.z*b0.z + b0.w*b0.w
                   + b1.x*b1.x + b1.y*b1.y + b1.z*b1.z + b1.w*b1.w
                   + b2.x*b2.x + b2.y*b2.y + b2.z*b2.z + b2.w*b2.w
                   + b3.x*b3.x + b3.y*b3.y + b3.z*b3.z + b3.w*b3.w;

        // 3-round 8-lane group butterfly — afterwards ALL lanes hold the sums
        #pragma unroll
        for (int o = 4; o; o >>= 1) {
            dota += __shfl_xor_sync(0xFFFFFFFFu, dota, o);
            nra  += __shfl_xor_sync(0xFFFFFFFFu, nra,  o);
            dotb += __shfl_xor_sync(0xFFFFFFFFu, dotb, o);
            nrb  += __shfl_xor_sync(0xFFFFFFFFu, nrb,  o);
        }

        // all-lane atomic-free epilogue: every lane owns a distinct smem address
        const float dt  = (e < 4) ? dota : dotb;
        const float nr  = (e < 4) ? nra  : nrb;
        const float sim = dt * rsqrtf(nr) * inv_qn;     // eps never binds (norms ~11)
        const float t   = (1.0f - sim) * 12.0f;
        const float mf  = floorf(t);
        const int   m0  = (int)mf;                      // in [-1, 24] for any fp edge
        const float fr  = t - mf;
        float w = (role & 1) ? fr : (1.0f - fr);
        if (role & 2) w *= (float)lab;                  // branchless label gate
        hbase[m0] += w;                                 // LDS+FADD+STS, race-free
        if (role == 0) labcnt += (float)lab;            // doc counted once (e==0, e==4)
    }

    #pragma unroll
    for (int o = 16; o; o >>= 1) labcnt += __shfl_xor_sync(0xFFFFFFFFu, labcnt, o);
    if (lane == 0) s_wl[warp] = labcnt;
    __syncthreads();

    // merge the 64 private copies (bins at slot n+1) into global accumulators
    for (int idx = tid; idx < 2 * NBIN_; idx += 256) {
        const int arr = idx / NBIN_, n = idx % NBIN_;
        float s = 0.0f;
        #pragma unroll
        for (int c = 0; c < 64; c++)
            s += s_hist[(c * 2 + arr) * NSLOT_ + n + 1];
        if (arr) atomicAdd(&g_hll[b][n], s);
        else     atomicAdd(&g_hla[b][n], s);
    }
    if (tid == 0) {
        float s = 0.0f;
        #pragma unroll
        for (int w = 0; w < 8; w++) s += s_wl[w];
        atomicAdd(&g_lsum[b], s);
    }

    __threadfence();
    __syncthreads();
    if (tid == 0) {
        unsigned prev = atomicAdd(&g_ticket, 1u);
        s_last = (prev == TOTAL_ - 1u);
    }
    __syncthreads();
    if (!s_last) return;

    // ---------------- last block: finalize + reset state ----------------
    __shared__ float f_hl[B_][NBIN_];
    __shared__ float f_ha[B_][NBIN_];
    __shared__ float f_ls[B_];

    for (int idx = tid; idx < B_ * NBIN_; idx += 256) {
        const int bb = idx / NBIN_, n = idx % NBIN_;
        f_hl[bb][n] = __ldcg(&g_hll[bb][n]);
        f_ha[bb][n] = __ldcg(&g_hla[bb][n]);
        g_hll[bb][n] = 0.0f;
        g_hla[bb][n] = 0.0f;
    }
    if (tid < B_) {
        f_ls[tid] = __ldcg(&g_lsum[tid]);
        g_lsum[tid] = 0.0f;
    }
    __syncthreads();

    float apq = 0.0f;
    if (tid < B_) {
        float cl = 0.0f, ca = 0.0f, s = 0.0f;
        const float inv_lab = 1.0f / f_ls[tid];
        #pragma unroll
        for (int n = 0; n < NBIN_; n++) {
            const float vhl = f_hl[tid][n];
            cl += vhl;
            ca += f_ha[tid][n];
            s += (cl / (ca + 1e-16f)) * (vhl * inv_lab);
        }
        apq = s / (float)NBIN_;
    }
    if (tid < 32) {
        #pragma unroll
        for (int o = 16; o; o >>= 1) apq += __shfl_xor_sync(0xFFFFFFFFu, apq, o);
        if (tid == 0) {
            out[0] = apq / (float)B_;
            g_ticket = 0u;
        }
    }
}

extern "C" void kernel_launch(void* const* d_in, const int* in_sizes, int n_in,
                              void* d_out, int out_size) {
    const float* qX     = (const float*)d_in[0];
    const float* dXs    = (const float*)d_in[1];
    const int*   labels = (const int*)d_in[2];
    float*       out    = (float*)d_out;

    qap_fused<<<dim3(G_, B_), 256>>>(qX, dXs, labels, out);
}